// round 4
// baseline (speedup 1.0000x reference)
#include <cuda_runtime.h>

#define BSZ 2
#define SEQ 4096
#define DIM 1024
#define CHUNK 32
#define NCHUNK (SEQ / CHUNK)  // 128

// ---- scratch (__device__ globals; no allocation allowed) ----
__device__ int   g_pos[BSZ * SEQ];          // boundary token original positions
__device__ float g_pk [BSZ * SEQ];          // clipped p at boundary k
__device__ float g_Pc [BSZ * NCHUNK];       // per-chunk decay product (scalar)
__device__ int   g_nb [BSZ];                // number of boundary tokens
__device__ float g_E  [BSZ * NCHUNK * DIM]; // chunk-end local states
__device__ float g_S  [BSZ * NCHUNK * DIM]; // incoming state per chunk

// ---------------------------------------------------------------------------
// Kernel 1: mask scan -> pos/pk/nb + per-chunk scalar decay products.
// One block per batch, 1024 threads (4 elems each).
// ---------------------------------------------------------------------------
__global__ void prep_kernel(const float* __restrict__ prob,
                            const void* __restrict__ mask_raw) {
    const int b = blockIdx.x;
    const int t = threadIdx.x;

    __shared__ int s_w;        // 1 => mask is 1 byte/elem
    __shared__ int s_wsum[32];
    __shared__ int s_total;

    // ---- detect mask element width ----
    // For 4-byte 0/1 values (int/float), bytes at offset 4j+1 are always 0.
    // For 1-byte bool at ~25% density some are nonzero w.p. ~1.
    if (t == 0) s_w = 0;
    __syncthreads();
    {
        const unsigned char* mb = (const unsigned char*)mask_raw;
        int f = 0;
        for (int j = t; j < (BSZ * SEQ) / 4; j += blockDim.x)
            f |= mb[4 * j + 1];
        if (f) s_w = 1;
    }
    __syncthreads();
    const int onebyte = s_w;

    // ---- load 4 mask values per thread ----
    const int base = t * 4;
    int m[4];
    if (onebyte) {
        const unsigned char* mb = (const unsigned char*)mask_raw + b * SEQ;
        #pragma unroll
        for (int j = 0; j < 4; j++) m[j] = mb[base + j] ? 1 : 0;
    } else {
        const int* mi = (const int*)mask_raw + b * SEQ;
        #pragma unroll
        for (int j = 0; j < 4; j++) m[j] = mi[base + j] ? 1 : 0;
    }
    int cnt = m[0] + m[1] + m[2] + m[3];

    // ---- block inclusive scan of per-thread counts ----
    int v = cnt;
    const int lane = t & 31, wid = t >> 5;
    #pragma unroll
    for (int o = 1; o < 32; o <<= 1) {
        int u = __shfl_up_sync(0xffffffffu, v, o);
        if (lane >= o) v += u;
    }
    if (lane == 31) s_wsum[wid] = v;
    __syncthreads();
    if (wid == 0) {
        int w = s_wsum[lane];
        #pragma unroll
        for (int o = 1; o < 32; o <<= 1) {
            int u = __shfl_up_sync(0xffffffffu, w, o);
            if (lane >= o) w += u;
        }
        s_wsum[lane] = w;
        if (lane == 31) s_total = w;
    }
    __syncthreads();

    int run = v - cnt + (wid ? s_wsum[wid - 1] : 0);  // exclusive prefix
    const int nb = s_total;
    if (t == 0) g_nb[b] = nb;

    const float* pb = prob + b * SEQ;
    #pragma unroll
    for (int j = 0; j < 4; j++) {
        const int l = base + j;
        if (m[j]) {
            float p = pb[l];
            p = fminf(fmaxf(p, 1e-4f), 0.9999f);
            g_pos[b * SEQ + run] = l;
            g_pk [b * SEQ + run] = p;
            run++;
        }
    }
    __syncthreads();  // g_pk visible within block (CTA-scope)

    // ---- per-chunk scalar decay products of a = 1-p ----
    for (int c = t; c < NCHUNK && c * CHUNK < nb; c += blockDim.x) {
        float q = 1.f;
        const int n = min(CHUNK, nb - c * CHUNK);
        for (int j = 0; j < n; j++)
            q *= (1.f - g_pk[b * SEQ + c * CHUNK + j]);
        g_Pc[b * NCHUNK + c] = q;
    }
}

// ---------------------------------------------------------------------------
// Kernel 2: chunk-local scans from zero -> chunk-end states g_E only.
// grid (DIM/256, NCHUNK, BSZ), 256 threads.
// ---------------------------------------------------------------------------
__global__ void escan_kernel(const float* __restrict__ hidden) {
    const int b = blockIdx.z, c = blockIdx.y;
    const int d = blockIdx.x * blockDim.x + threadIdx.x;
    const int nb = g_nb[b];
    const int k0 = c * CHUNK;
    if (k0 >= nb) return;
    const int n = min(CHUNK, nb - k0);

    __shared__ int   spos[CHUNK];
    __shared__ float spk [CHUNK];
    if (threadIdx.x < n) {
        spos[threadIdx.x] = g_pos[b * SEQ + k0 + threadIdx.x];
        spk [threadIdx.x] = g_pk [b * SEQ + k0 + threadIdx.x];
    }
    __syncthreads();

    const float* hb = hidden + (size_t)b * SEQ * DIM + d;
    float h[CHUNK];
    #pragma unroll
    for (int j = 0; j < CHUNK; j++)
        h[j] = (j < n) ? __ldg(hb + (size_t)spos[j] * DIM) : 0.f;

    float s = 0.f;
    #pragma unroll
    for (int j = 0; j < CHUNK; j++) {
        if (j < n) {
            const float p = spk[j];
            s = fmaf(1.f - p, s, p * h[j]);
        }
    }
    g_E[(b * NCHUNK + c) * DIM + d] = s;
}

// ---------------------------------------------------------------------------
// Kernel 3: serial combine across chunks per channel -> g_S (incoming states).
// grid (DIM/256, BSZ), 256 threads.
// ---------------------------------------------------------------------------
__global__ void combine_kernel() {
    const int b = blockIdx.y;
    const int d = blockIdx.x * blockDim.x + threadIdx.x;
    const int nb = g_nb[b];
    const int nc = (nb + CHUNK - 1) / CHUNK;

    const float* Eb = g_E + (b * NCHUNK) * DIM + d;
    const float* Pb = g_Pc + b * NCHUNK;
    float*       Sb = g_S + (b * NCHUNK) * DIM + d;

    float s = 0.f;
    const int G = 16;
    float Ebuf[G], Pbuf[G];
    #pragma unroll
    for (int j = 0; j < G; j++) {
        Ebuf[j] = (j < nc) ? Eb[j * DIM] : 0.f;
        Pbuf[j] = (j < nc) ? Pb[j] : 1.f;
    }
    for (int g = 0; g < NCHUNK && g < nc; g += G) {
        float En[G], Pn[G];
        #pragma unroll
        for (int j = 0; j < G; j++) {
            const int cc = g + G + j;
            En[j] = (cc < nc) ? Eb[cc * DIM] : 0.f;
            Pn[j] = (cc < nc) ? Pb[cc] : 1.f;
        }
        #pragma unroll
        for (int j = 0; j < G; j++) {
            const int cc = g + j;
            if (cc < nc) {
                Sb[cc * DIM] = s;
                s = fmaf(Pbuf[j], s, Ebuf[j]);
            }
        }
        #pragma unroll
        for (int j = 0; j < G; j++) { Ebuf[j] = En[j]; Pbuf[j] = Pn[j]; }
    }
}

// ---------------------------------------------------------------------------
// Kernel 4: fused re-scan (seeded with S[c]) + run-expansion to out.
// Linear recurrence => seeding with the incoming chunk state gives the
// fully-combined value y_k directly. Token k's value is written to
// out[l,:] for l in [start_k, end_k) where runs tile [0, SEQ).
// grid (DIM/256, NCHUNK, BSZ), 256 threads.
// ---------------------------------------------------------------------------
__global__ void fused_out_kernel(const float* __restrict__ hidden,
                                 float* __restrict__ out) {
    const int b = blockIdx.z, c = blockIdx.y;
    const int d = blockIdx.x * blockDim.x + threadIdx.x;
    const int nb = g_nb[b];
    const int k0 = c * CHUNK;
    if (k0 >= nb) return;
    const int n = min(CHUNK, nb - k0);

    __shared__ int   spos[CHUNK + 1];
    __shared__ float spk [CHUNK];
    if (threadIdx.x <= n) {
        const int kk = k0 + threadIdx.x;
        spos[threadIdx.x] = (kk < nb) ? g_pos[b * SEQ + kk] : SEQ;
    }
    if (threadIdx.x < n)
        spk[threadIdx.x] = g_pk[b * SEQ + k0 + threadIdx.x];
    __syncthreads();

    const float* hb = hidden + (size_t)b * SEQ * DIM + d;
    float h[CHUNK];
    #pragma unroll
    for (int j = 0; j < CHUNK; j++)
        h[j] = (j < n) ? __ldg(hb + (size_t)spos[j] * DIM) : 0.f;

    float s = g_S[(size_t)(b * NCHUNK + c) * DIM + d];  // incoming chunk state
    float* ob = out + (size_t)b * SEQ * DIM + d;

    #pragma unroll
    for (int j = 0; j < CHUNK; j++) {
        if (j < n) {
            const float p = spk[j];
            s = fmaf(1.f - p, s, p * h[j]);
            // run for token k0+j: [start, end)  (k==0 covers leading clip region)
            const int start = (k0 + j == 0) ? 0 : spos[j];
            const int end = spos[j + 1];
            for (int l = start; l < end; l++)
                ob[(size_t)l * DIM] = s;
        }
    }
}

// ---------------------------------------------------------------------------
extern "C" void kernel_launch(void* const* d_in, const int* in_sizes, int n_in,
                              void* d_out, int out_size) {
    const float* hidden = (const float*)d_in[0];
    const float* prob   = (const float*)d_in[1];
    const void*  mask   = d_in[2];
    float* out = (float*)d_out;

    prep_kernel<<<BSZ, 1024>>>(prob, mask);
    escan_kernel<<<dim3(DIM / 256, NCHUNK, BSZ), 256>>>(hidden);
    combine_kernel<<<dim3(DIM / 256, BSZ), 256>>>();
    fused_out_kernel<<<dim3(DIM / 256, NCHUNK, BSZ), 256>>>(hidden, out);
}